// round 2
// baseline (speedup 1.0000x reference)
#include <cuda_runtime.h>
#include <cuda_bf16.h>
#include <cstdint>

// Problem constants
#define B_  4
#define H_  8
#define LQ_ 256
#define LK_ 256
#define DK_ 64
#define BH_ (B_*H_)                 // 32
#define NQROWS (BH_*LQ_)            // 8192
#define NKROWS (BH_*LK_)            // 8192

// Scratch for projected q and k: rows [0,8192) = qp, [8192,16384) = kp
__device__ float g_proj[(NQROWS + NKROWS) * DK_];   // 4 MB

__device__ __forceinline__ float tanh_fast(float x) {
    float y;
    asm("tanh.approx.f32 %0, %1;" : "=f"(y) : "f"(x));
    return y;
}
__device__ __forceinline__ float ex2_fast(float x) {
    float y;
    asm("ex2.approx.f32 %0, %1;" : "=f"(y) : "f"(x));
    return y;
}

// ---------------------------------------------------------------------------
// Kernel 1: projections. qp = q @ Wq^T + bq ; kp = k @ Wk^T + bk
// grid 256 CTAs x 256 thr. CTA handles 64 rows; thread = (row, 16-wide e-slice).
// ---------------------------------------------------------------------------
__global__ __launch_bounds__(256) void proj_kernel(
    const float4* __restrict__ q4, const float4* __restrict__ k4,
    const float* __restrict__ Wq, const float* __restrict__ bq,
    const float* __restrict__ Wk, const float* __restrict__ bk)
{
    __shared__ float wt[64 * 64];    // transposed: wt[d][e]
    __shared__ float bs[64];
    const int tid = threadIdx.x;
    const bool isK = (blockIdx.x >= 128);
    const float* W    = isK ? Wk : Wq;
    const float* bias = isK ? bk : bq;

    for (int i = tid; i < 4096; i += 256)
        wt[(i & 63) * 64 + (i >> 6)] = W[i];      // wt[d*64+e] = W[e*64+d]
    if (tid < 64) bs[tid] = bias[tid];

    const int row  = blockIdx.x * 64 + (tid >> 2);   // 0..16383
    const int e0   = (tid & 3) * 16;
    const int srow = isK ? (row - NQROWS) : row;
    const float4* src = isK ? k4 : q4;

    float x[64];
#pragma unroll
    for (int j = 0; j < 16; j++) {
        float4 t = src[srow * 16 + j];
        x[4*j+0] = t.x; x[4*j+1] = t.y; x[4*j+2] = t.z; x[4*j+3] = t.w;
    }
    __syncthreads();

    float acc[16];
#pragma unroll
    for (int j = 0; j < 16; j++) acc[j] = bs[e0 + j];

#pragma unroll 8
    for (int d = 0; d < 64; d++) {
        const float xd = x[d];
#pragma unroll
        for (int j = 0; j < 16; j++)
            acc[j] = fmaf(xd, wt[d * 64 + e0 + j], acc[j]);
    }

    float4* dst = (float4*)(g_proj + row * 64 + e0);
#pragma unroll
    for (int j = 0; j < 4; j++)
        dst[j] = make_float4(acc[4*j+0], acc[4*j+1], acc[4*j+2], acc[4*j+3]);
}

// ---------------------------------------------------------------------------
// Kernel 2: fused additive attention.
// grid = BH * (LQ/32) = 256 CTAs, 256 thr (8 warps), 2 CTAs/SM.
// Warp lanes = 32 q rows (qp in 64 regs/lane); warp w owns k-chunk [32w,32w+32).
// kp[k][d] / w[d] shared-loads are pure broadcasts (conflict-free).
// Scores in smem s_s[k*33 + q] (pitch 33 => conflict-free in every pass).
// Softmax across warps via smem partials, then epilogue attn@v from smem v.
// ---------------------------------------------------------------------------
#define SM_KP   0                    // 16384 floats (kp tile, later reused for v)
#define SM_S    16384                // 256*33 = 8448 floats
#define SM_W    (16384 + 8448)       // 64
#define SM_CMAX (SM_W + 64)          // 256
#define SM_CSUM (SM_CMAX + 256)      // 256
#define SM_M    (SM_CSUM + 256)      // 32
#define SM_R    (SM_M + 32)          // 32
#define SM_FLOATS (SM_R + 32)        // 25472 floats = 101888 bytes

__global__ __launch_bounds__(256, 2) void attn_kernel(
    const float* __restrict__ v,
    const float* __restrict__ vs_w,
    float* __restrict__ out,        // [BH,256,64]
    float* __restrict__ attn_out)   // [BH,256,256]
{
    extern __shared__ float sm[];
    float* kp_s = sm + SM_KP;
    float* s_s  = sm + SM_S;
    float* w_s  = sm + SM_W;
    float* cmax = sm + SM_CMAX;
    float* csum = sm + SM_CSUM;
    float* m_s  = sm + SM_M;
    float* r_s  = sm + SM_R;

    const int tid  = threadIdx.x;
    const int wid  = tid >> 5;
    const int lane = tid & 31;
    const int bh   = blockIdx.x >> 3;
    const int qt   = blockIdx.x & 7;

    // cooperative load of kp tile [256][64] for this bh
    {
        const float4* src = (const float4*)(g_proj + (NQROWS + bh * LK_) * DK_);
        float4* dst = (float4*)kp_s;
        for (int i = tid; i < 4096; i += 256) dst[i] = src[i];
    }
    if (tid < 64) w_s[tid] = vs_w[tid];

    // this lane's qp row (64 regs)
    const int qrow = bh * LQ_ + qt * 32 + lane;
    float qp[64];
    {
        const float4* qsrc = (const float4*)(g_proj + qrow * 64);
#pragma unroll
        for (int j = 0; j < 16; j++) {
            float4 t = qsrc[j];
            qp[4*j+0] = t.x; qp[4*j+1] = t.y; qp[4*j+2] = t.z; qp[4*j+3] = t.w;
        }
    }
    __syncthreads();

    // ---- main loop: scores for k in [32*wid, 32*wid+32) -------------------
    const int k0 = wid * 32;
    float cm = -1e30f;
    for (int kk = 0; kk < 32; kk++) {
        const int k = k0 + kk;
        const float* kr = kp_s + k * 64;
        float a0 = 0.f, a1 = 0.f, a2 = 0.f, a3 = 0.f;
#pragma unroll
        for (int d = 0; d < 64; d += 4) {
            a0 = fmaf(tanh_fast(qp[d+0] + kr[d+0]), w_s[d+0], a0);
            a1 = fmaf(tanh_fast(qp[d+1] + kr[d+1]), w_s[d+1], a1);
            a2 = fmaf(tanh_fast(qp[d+2] + kr[d+2]), w_s[d+2], a2);
            a3 = fmaf(tanh_fast(qp[d+3] + kr[d+3]), w_s[d+3], a3);
        }
        const float acc = (a0 + a1) + (a2 + a3);
        s_s[k * 33 + lane] = acc;
        cm = fmaxf(cm, acc);
    }
    cmax[wid * 32 + lane] = cm;
    __syncthreads();

    // ---- softmax ----------------------------------------------------------
    if (wid == 0) {
        float m = cmax[lane];
#pragma unroll
        for (int w = 1; w < 8; w++) m = fmaxf(m, cmax[w * 32 + lane]);
        m_s[lane] = m;
    }
    __syncthreads();
    {
        const float m = m_s[lane];
        float s = 0.f;
        for (int kk = 0; kk < 32; kk++) {
            const int k = k0 + kk;
            const float e = ex2_fast((s_s[k * 33 + lane] - m) * 1.4426950408889634f);
            s_s[k * 33 + lane] = e;   // store unnormalized p
            s += e;
        }
        csum[wid * 32 + lane] = s;
    }
    __syncthreads();
    if (wid == 0) {
        float l = csum[lane];
#pragma unroll
        for (int w = 1; w < 8; w++) l += csum[w * 32 + lane];
        r_s[lane] = 1.0f / l;
    }
    __syncthreads();

    // ---- write attn (coalesced) + stage v into smem (reuse kp_s) ----------
    {
        const float4* vsrc = (const float4*)(v + bh * (LK_ * DK_));
        float4* vdst = (float4*)kp_s;
        for (int i = tid; i < 4096; i += 256) vdst[i] = vsrc[i];
    }
    {
        float* ab = attn_out + (bh * LQ_ + qt * 32) * LK_;
        for (int i = 0; i < 32; i++) {
            const int q = i, k = tid;              // 256 threads = full k row
            ab[q * LK_ + k] = s_s[k * 33 + q] * r_s[q];
        }
    }
    __syncthreads();

    // ---- epilogue: out[q][d] = sum_k p[q][k]*v[k][d] * r[q] ---------------
    // warp wid owns q' in [4*wid, 4*wid+4); lane covers d=lane and d=lane+32
    {
        const float* v_s = kp_s;
        const int qb = wid * 4;
        float acc0[4] = {0.f, 0.f, 0.f, 0.f};
        float acc1[4] = {0.f, 0.f, 0.f, 0.f};
#pragma unroll 4
        for (int k = 0; k < 256; k++) {
            const float v0 = v_s[k * 64 + lane];
            const float v1 = v_s[k * 64 + 32 + lane];
#pragma unroll
            for (int j = 0; j < 4; j++) {
                const float p = s_s[k * 33 + qb + j];   // broadcast
                acc0[j] = fmaf(p, v0, acc0[j]);
                acc1[j] = fmaf(p, v1, acc1[j]);
            }
        }
        float* ob = out + (bh * LQ_ + qt * 32) * DK_;
#pragma unroll
        for (int j = 0; j < 4; j++) {
            const float r = r_s[qb + j];
            ob[(qb + j) * DK_ + lane]      = acc0[j] * r;
            ob[(qb + j) * DK_ + 32 + lane] = acc1[j] * r;
        }
    }
}

// ---------------------------------------------------------------------------
extern "C" void kernel_launch(void* const* d_in, const int* in_sizes, int n_in,
                              void* d_out, int out_size)
{
    const float* q    = (const float*)d_in[0];
    const float* k    = (const float*)d_in[1];
    const float* v    = (const float*)d_in[2];
    const float* Wq_w = (const float*)d_in[3];
    const float* Wq_b = (const float*)d_in[4];
    const float* Wk_w = (const float*)d_in[5];
    const float* Wk_b = (const float*)d_in[6];
    const float* vs_w = (const float*)d_in[7];
    // vs_b (d_in[8]) is softmax-invariant: unused.

    float* out  = (float*)d_out;                       // [B,H,LQ,DK]
    float* attn = (float*)d_out + (size_t)BH_ * LQ_ * DK_;  // [B,H,LQ,LK]

    const int smem_bytes = SM_FLOATS * 4;
    cudaFuncSetAttribute(attn_kernel, cudaFuncAttributeMaxDynamicSharedMemorySize,
                         smem_bytes);

    proj_kernel<<<256, 256>>>((const float4*)q, (const float4*)k,
                              Wq_w, Wq_b, Wk_w, Wk_b);
    attn_kernel<<<256, 256, smem_bytes>>>(v, vs_w, out, attn);
}

// round 3
// speedup vs baseline: 1.0312x; 1.0312x over previous
#include <cuda_runtime.h>
#include <cuda_bf16.h>
#include <cstdint>

#define B_  4
#define H_  8
#define LQ_ 256
#define LK_ 256
#define DK_ 64
#define BH_ (B_*H_)                 // 32
#define NQROWS (BH_*LQ_)            // 8192
#define NKROWS (BH_*LK_)            // 8192
#define LOG2E 1.4426950408889634f

typedef unsigned long long ull;

// Scratch: rows [0,8192) = qp, [8192,16384) = kp
__device__ float g_proj[(NQROWS + NKROWS) * DK_];   // 4 MB

// ---------------- packed-math helpers -------------------------------------
__device__ __forceinline__ ull pk(float lo, float hi) {
    ull r; asm("mov.b64 %0,{%1,%2};" : "=l"(r) : "f"(lo), "f"(hi)); return r;
}
__device__ __forceinline__ void upk(ull v, float& lo, float& hi) {
    asm("mov.b64 {%0,%1},%2;" : "=f"(lo), "=f"(hi) : "l"(v));
}
__device__ __forceinline__ ull add2(ull a, ull b) {
    ull r; asm("add.rn.f32x2 %0,%1,%2;" : "=l"(r) : "l"(a), "l"(b)); return r;
}
__device__ __forceinline__ ull fma2(ull a, ull b, ull c) {
    ull r; asm("fma.rn.f32x2 %0,%1,%2,%3;" : "=l"(r) : "l"(a), "l"(b), "l"(c)); return r;
}
// f16x2 pack: first PTX operand -> HIGH half
__device__ __forceinline__ uint32_t cvt_h2(float hi, float lo) {
    uint32_t r; asm("cvt.rn.f16x2.f32 %0,%1,%2;" : "=r"(r) : "f"(hi), "f"(lo)); return r;
}
__device__ __forceinline__ uint32_t tanh2(uint32_t x) {
    uint32_t y; asm("tanh.approx.f16x2 %0,%1;" : "=r"(y) : "r"(x)); return y;
}
__device__ __forceinline__ uint32_t hmul2(uint32_t a, uint32_t b) {
    uint32_t r; asm("mul.f16x2 %0,%1,%2;" : "=r"(r) : "r"(a), "r"(b)); return r;
}
__device__ __forceinline__ void h2tof(uint32_t h, float& lo, float& hi) {
    asm("{.reg .b16 l,h; mov.b32 {l,h},%2; cvt.f32.f16 %0,l; cvt.f32.f16 %1,h;}"
        : "=f"(lo), "=f"(hi) : "r"(h));
}
__device__ __forceinline__ float ex2_fast(float x) {
    float y; asm("ex2.approx.f32 %0,%1;" : "=f"(y) : "f"(x)); return y;
}

// one additive-attention term pair: acc += f32(tanh_f16(qp+kp)) * w  (2 elems)
__device__ __forceinline__ void term(ull qp2, ull kv2, uint32_t w2, ull& acc) {
    ull s = add2(qp2, kv2);
    float lo, hi; upk(s, lo, hi);
    uint32_t t = tanh2(cvt_h2(hi, lo));
    uint32_t p = hmul2(t, w2);
    float plo, phi; h2tof(p, plo, phi);
    acc = add2(acc, pk(plo, phi));
}

// ---------------------------------------------------------------------------
// Kernel 1: projections. grid 512 CTAs x 256 thr, 32 rows per CTA.
// thread = (r = tid>>3, e-slice of 8). W transposed in smem (pitch 68).
// ---------------------------------------------------------------------------
__global__ __launch_bounds__(256) void proj_kernel(
    const float* __restrict__ q, const float* __restrict__ k,
    const float* __restrict__ Wq, const float* __restrict__ bq,
    const float* __restrict__ Wk, const float* __restrict__ bk)
{
    __shared__ float wt[64 * 68];     // wt[d*68+e] = W[e][d]
    __shared__ float xs[32 * 64];
    __shared__ float bs[64];
    const int tid = threadIdx.x;
    const bool isK = (blockIdx.x >= 256);
    const float* W    = isK ? Wk : Wq;
    const float* bias = isK ? bk : bq;
    const float* src  = isK ? k : q;
    const int rowbase = (blockIdx.x & 255) * 32;

    for (int i = tid; i < 4096; i += 256)
        wt[(i & 63) * 68 + (i >> 6)] = W[i];
    if (tid < 64) bs[tid] = bias[tid];
    {
        const float4* s4 = (const float4*)(src + rowbase * 64);
        ((float4*)xs)[tid]       = s4[tid];
        ((float4*)xs)[tid + 256] = s4[tid + 256];
    }
    __syncthreads();

    const int r  = tid >> 3;
    const int e0 = (tid & 7) * 8;
    ull acc[4];
#pragma unroll
    for (int j = 0; j < 4; j++) acc[j] = pk(bs[e0 + 2*j], bs[e0 + 2*j + 1]);

#pragma unroll 8
    for (int d = 0; d < 64; d++) {
        const float xd = xs[r * 64 + d];
        const ull xx = pk(xd, xd);
        const float4 wA = *(const float4*)(wt + d * 68 + e0);
        const float4 wB = *(const float4*)(wt + d * 68 + e0 + 4);
        acc[0] = fma2(xx, pk(wA.x, wA.y), acc[0]);
        acc[1] = fma2(xx, pk(wA.z, wA.w), acc[1]);
        acc[2] = fma2(xx, pk(wB.x, wB.y), acc[2]);
        acc[3] = fma2(xx, pk(wB.z, wB.w), acc[3]);
    }

    float o[8];
#pragma unroll
    for (int j = 0; j < 4; j++) upk(acc[j], o[2*j], o[2*j+1]);
    float* dst = g_proj + (size_t)(isK ? NQROWS : 0) * 64 + (rowbase + r) * 64 + e0;
    *(float4*)dst       = make_float4(o[0], o[1], o[2], o[3]);
    *(float4*)(dst + 4) = make_float4(o[4], o[5], o[6], o[7]);
}

// ---------------------------------------------------------------------------
// Kernel 2: fused additive attention.
// grid = 256 CTAs (bh x q-tile of 32), 256 thr (8 warps), 2 CTAs/SM.
// lanes = 32 q rows; warp wid owns k-chunk [32*wid, 32*wid+32).
// tanh path: f32 add -> f16x2 tanh -> f16 mul by w -> f32x2 accumulate.
// Scores in s_s[k*36 + q] (conflict-free + 16B aligned rows).
// ---------------------------------------------------------------------------
#define SM_KP   0                          // 16384 floats (kp, later v)
#define SM_S    16384                      // 256*36 = 9216 floats
#define SM_W    (SM_S + 9216)              // 64
#define SM_CMAX (SM_W + 64)                // 256
#define SM_CSUM (SM_CMAX + 256)            // 256
#define SM_M    (SM_CSUM + 256)            // 32
#define SM_R    (SM_M + 32)                // 32
#define SM_FLOATS (SM_R + 32)              // 26240 floats = 104960 B

__global__ __launch_bounds__(256, 2) void attn_kernel(
    const float* __restrict__ v,
    const float* __restrict__ vs_w,
    float* __restrict__ out,        // [BH,256,64]
    float* __restrict__ attn_out)   // [BH,256,256]
{
    extern __shared__ float sm[];
    float* kp_s = sm + SM_KP;
    float* s_s  = sm + SM_S;
    float* w_s  = sm + SM_W;
    float* cmax = sm + SM_CMAX;
    float* csum = sm + SM_CSUM;
    float* m_s  = sm + SM_M;
    float* r_s  = sm + SM_R;

    const int tid  = threadIdx.x;
    const int wid  = tid >> 5;
    const int lane = tid & 31;
    const int bh   = blockIdx.x >> 3;
    const int qt   = blockIdx.x & 7;

    // cooperative kp tile load [256][64]
    {
        const float4* src = (const float4*)(g_proj + (size_t)(NQROWS + bh * LK_) * DK_);
        float4* dst = (float4*)kp_s;
        for (int i = tid; i < 4096; i += 256) dst[i] = src[i];
    }
    if (tid < 64) w_s[tid] = vs_w[tid];

    // qp row for this lane, packed as f32x2 (32 x u64)
    const int qrow = bh * LQ_ + qt * 32 + lane;
    ull qp2[32];
    {
        const float4* qsrc = (const float4*)(g_proj + (size_t)qrow * 64);
#pragma unroll
        for (int j = 0; j < 16; j++) {
            float4 t = qsrc[j];
            qp2[2*j]   = pk(t.x, t.y);
            qp2[2*j+1] = pk(t.z, t.w);
        }
    }
    __syncthreads();

    // w as f16x2 in registers (lo = w[2i], hi = w[2i+1])
    uint32_t w2h[32];
#pragma unroll
    for (int i = 0; i < 32; i++) w2h[i] = cvt_h2(w_s[2*i+1], w_s[2*i]);

    // ---- main loop ---------------------------------------------------------
    const int k0 = wid * 32;
    float cm = -1e30f;
#pragma unroll 1
    for (int kk = 0; kk < 32; kk++) {
        const int k = k0 + kk;
        const float4* kr4 = (const float4*)(kp_s + k * 64);
        ull a0 = 0, a1 = 0;
#pragma unroll
        for (int j = 0; j < 16; j++) {
            float4 kv = kr4[j];
            term(qp2[2*j],   pk(kv.x, kv.y), w2h[2*j],   a0);
            term(qp2[2*j+1], pk(kv.z, kv.w), w2h[2*j+1], a1);
        }
        float f0, f1, f2, f3;
        upk(a0, f0, f1); upk(a1, f2, f3);
        const float sc = (f0 + f1) + (f2 + f3);
        s_s[k * 36 + lane] = sc;
        cm = fmaxf(cm, sc);
    }
    cmax[wid * 32 + lane] = cm;
    __syncthreads();

    // ---- row max + stage v into kp_s (kp no longer needed) -----------------
    if (wid == 0) {
        float m = cmax[lane];
#pragma unroll
        for (int w = 1; w < 8; w++) m = fmaxf(m, cmax[w * 32 + lane]);
        m_s[lane] = m;
    }
    {
        const float4* vsrc = (const float4*)(v + (size_t)bh * (LK_ * DK_));
        float4* vdst = (float4*)kp_s;
        for (int i = tid; i < 4096; i += 256) vdst[i] = vsrc[i];
    }
    __syncthreads();

    // ---- exp pass ----------------------------------------------------------
    {
        const float m = m_s[lane];
        float s = 0.f;
#pragma unroll 4
        for (int kk = 0; kk < 32; kk++) {
            const int k = k0 + kk;
            const float e = ex2_fast((s_s[k * 36 + lane] - m) * LOG2E);
            s_s[k * 36 + lane] = e;
            s += e;
        }
        csum[wid * 32 + lane] = s;
    }
    __syncthreads();
    if (wid == 0) {
        float l = csum[lane];
#pragma unroll
        for (int w = 1; w < 8; w++) l += csum[w * 32 + lane];
        r_s[lane] = 1.0f / l;
    }
    __syncthreads();

    // ---- write attn (coalesced) -------------------------------------------
    {
        float* ab = attn_out + (size_t)(bh * LQ_ + qt * 32) * LK_;
#pragma unroll 4
        for (int i = 0; i < 32; i++)
            ab[i * LK_ + tid] = s_s[tid * 36 + i] * r_s[i];
    }

    // ---- epilogue: out[q][d] = (sum_k e[q][k]*v[k][d]) * r[q] -------------
    // warp wid: q-octet qb = 8*(wid&3), d = 32*(wid>>2) + lane.
    {
        const int qb = (wid & 3) * 8;
        const int d  = ((wid >> 2) * 32) + lane;
        const float* vcol = kp_s + d;
        ull acc[4] = {0, 0, 0, 0};
#pragma unroll 4
        for (int k = 0; k < 256; k++) {
            const float vd = vcol[k * 64];
            const ull vv = pk(vd, vd);
            const float4 pA = *(const float4*)(s_s + k * 36 + qb);
            const float4 pB = *(const float4*)(s_s + k * 36 + qb + 4);
            acc[0] = fma2(vv, pk(pA.x, pA.y), acc[0]);
            acc[1] = fma2(vv, pk(pA.z, pA.w), acc[1]);
            acc[2] = fma2(vv, pk(pB.x, pB.y), acc[2]);
            acc[3] = fma2(vv, pk(pB.z, pB.w), acc[3]);
        }
        float* ob = out + (size_t)(bh * LQ_ + qt * 32 + qb) * DK_ + d;
#pragma unroll
        for (int j = 0; j < 4; j++) {
            float o0, o1; upk(acc[j], o0, o1);
            ob[(2*j)   * DK_] = o0 * r_s[qb + 2*j];
            ob[(2*j+1) * DK_] = o1 * r_s[qb + 2*j + 1];
        }
    }
}

// ---------------------------------------------------------------------------
extern "C" void kernel_launch(void* const* d_in, const int* in_sizes, int n_in,
                              void* d_out, int out_size)
{
    const float* q    = (const float*)d_in[0];
    const float* k    = (const float*)d_in[1];
    const float* v    = (const float*)d_in[2];
    const float* Wq_w = (const float*)d_in[3];
    const float* Wq_b = (const float*)d_in[4];
    const float* Wk_w = (const float*)d_in[5];
    const float* Wk_b = (const float*)d_in[6];
    const float* vs_w = (const float*)d_in[7];
    // vs_b (d_in[8]) is softmax-invariant: unused.

    float* out  = (float*)d_out;                            // [B,H,LQ,DK]
    float* attn = (float*)d_out + (size_t)BH_ * LQ_ * DK_;  // [B,H,LQ,LK]

    const int smem_bytes = SM_FLOATS * 4;
    cudaFuncSetAttribute(attn_kernel, cudaFuncAttributeMaxDynamicSharedMemorySize,
                         smem_bytes);

    proj_kernel<<<512, 256>>>(q, k, Wq_w, Wq_b, Wk_w, Wk_b);
    attn_kernel<<<256, 256, smem_bytes>>>(v, vs_w, out, attn);
}

// round 4
// speedup vs baseline: 1.1489x; 1.1141x over previous
#include <cuda_runtime.h>
#include <cuda_bf16.h>
#include <cstdint>

#define B_  4
#define H_  8
#define LQ_ 256
#define LK_ 256
#define DK_ 64
#define BH_ (B_*H_)                 // 32
#define NQROWS (BH_*LQ_)            // 8192
#define NKROWS (BH_*LK_)            // 8192
#define LOG2E 1.4426950408889634f

typedef unsigned long long ull;

// Projected q,k as f16x2 words: row r (0..16383), 32 words (64 dims).
// rows [0,8192) = qp, [8192,16384) = kp
__device__ uint32_t g_ph[(NQROWS + NKROWS) * 32];   // 2 MB

// ---------------- packed-math helpers -------------------------------------
__device__ __forceinline__ ull pk(float lo, float hi) {
    ull r; asm("mov.b64 %0,{%1,%2};" : "=l"(r) : "f"(lo), "f"(hi)); return r;
}
__device__ __forceinline__ void upk(ull v, float& lo, float& hi) {
    asm("mov.b64 {%0,%1},%2;" : "=f"(lo), "=f"(hi) : "l"(v));
}
__device__ __forceinline__ ull add2(ull a, ull b) {
    ull r; asm("add.rn.f32x2 %0,%1,%2;" : "=l"(r) : "l"(a), "l"(b)); return r;
}
__device__ __forceinline__ ull fma2(ull a, ull b, ull c) {
    ull r; asm("fma.rn.f32x2 %0,%1,%2,%3;" : "=l"(r) : "l"(a), "l"(b), "l"(c)); return r;
}
// f16x2 pack: first PTX operand -> HIGH half
__device__ __forceinline__ uint32_t cvt_h2(float hi, float lo) {
    uint32_t r; asm("cvt.rn.f16x2.f32 %0,%1,%2;" : "=r"(r) : "f"(hi), "f"(lo)); return r;
}
__device__ __forceinline__ uint32_t hadd2(uint32_t a, uint32_t b) {
    uint32_t r; asm("add.rn.f16x2 %0,%1,%2;" : "=r"(r) : "r"(a), "r"(b)); return r;
}
__device__ __forceinline__ uint32_t hfma2(uint32_t a, uint32_t b, uint32_t c) {
    uint32_t r; asm("fma.rn.f16x2 %0,%1,%2,%3;" : "=r"(r) : "r"(a), "r"(b), "r"(c)); return r;
}
__device__ __forceinline__ uint32_t tanh2(uint32_t x) {
    uint32_t y; asm("tanh.approx.f16x2 %0,%1;" : "=r"(y) : "r"(x)); return y;
}
__device__ __forceinline__ void h2tof(uint32_t h, float& lo, float& hi) {
    asm("{.reg .b16 l,h; mov.b32 {l,h},%2; cvt.f32.f16 %0,l; cvt.f32.f16 %1,h;}"
        : "=f"(lo), "=f"(hi) : "r"(h));
}
__device__ __forceinline__ float ex2_fast(float x) {
    float y; asm("ex2.approx.f32 %0,%1;" : "=f"(y) : "f"(x)); return y;
}

// ---------------------------------------------------------------------------
// Kernel 1: projections -> f16x2. grid 512 x 256 thr, 32 rows/CTA.
// ---------------------------------------------------------------------------
__global__ __launch_bounds__(256) void proj_kernel(
    const float* __restrict__ q, const float* __restrict__ k,
    const float* __restrict__ Wq, const float* __restrict__ bq,
    const float* __restrict__ Wk, const float* __restrict__ bk)
{
    __shared__ float wt[64 * 68];     // wt[d*68+e] = W[e][d]
    __shared__ float xs[32 * 64];
    __shared__ float bs[64];
    const int tid = threadIdx.x;
    const bool isK = (blockIdx.x >= 256);
    const float* W    = isK ? Wk : Wq;
    const float* bias = isK ? bk : bq;
    const float* src  = isK ? k : q;
    const int rowbase = (blockIdx.x & 255) * 32;

    for (int i = tid; i < 4096; i += 256)
        wt[(i & 63) * 68 + (i >> 6)] = W[i];
    if (tid < 64) bs[tid] = bias[tid];
    {
        const float4* s4 = (const float4*)(src + rowbase * 64);
        ((float4*)xs)[tid]       = s4[tid];
        ((float4*)xs)[tid + 256] = s4[tid + 256];
    }
    __syncthreads();

    const int r  = tid >> 3;
    const int e0 = (tid & 7) * 8;
    ull acc[4];
#pragma unroll
    for (int j = 0; j < 4; j++) acc[j] = pk(bs[e0 + 2*j], bs[e0 + 2*j + 1]);

#pragma unroll 8
    for (int d = 0; d < 64; d++) {
        const float xd = xs[r * 64 + d];
        const ull xx = pk(xd, xd);
        const float4 wA = *(const float4*)(wt + d * 68 + e0);
        const float4 wB = *(const float4*)(wt + d * 68 + e0 + 4);
        acc[0] = fma2(xx, pk(wA.x, wA.y), acc[0]);
        acc[1] = fma2(xx, pk(wA.z, wA.w), acc[1]);
        acc[2] = fma2(xx, pk(wB.x, wB.y), acc[2]);
        acc[3] = fma2(xx, pk(wB.z, wB.w), acc[3]);
    }

    uint32_t h[4];
#pragma unroll
    for (int j = 0; j < 4; j++) {
        float lo, hi; upk(acc[j], lo, hi);
        h[j] = cvt_h2(hi, lo);
    }
    const int row = (isK ? NQROWS : 0) + rowbase + r;
    *(uint4*)(g_ph + (size_t)row * 32 + (tid & 7) * 4) =
        make_uint4(h[0], h[1], h[2], h[3]);
}

// ---------------------------------------------------------------------------
// Kernel 2: fused additive attention.
// grid = 512 CTAs (32 bh x 16 q-tiles of 16 rows), 256 thr, 4 CTAs/SM.
// Warp wid owns k-chunk [32*wid,32*wid+32); lane = (q = lane&15, kh = lane>>4),
// lane covers k in [k0+16*kh, k0+16*kh+16).
// d processed in two halves of 32 (qp/w halves in regs: 16+16 u32).
// Inner op: HADD2 -> tanh.f16x2 -> HFMA2 (4-product f16 chains) -> f32 flush.
// Scores s_s[k*17+q] (conflict-free everywhere). v staged as f16x2 over kp.
// ---------------------------------------------------------------------------
// smem layout (float indices)
#define SM_KP    0        // 8192 u32  (kp f16x2, later v f16x2)
#define SM_W2H   8192     // 32 u32
#define SM_S     8224     // 4352 floats (256 x 17)
#define SM_PMAX  12576    // 16 x 17
#define SM_PSUM  12848    // 16 x 17
#define SM_M     13120    // 16
#define SM_R     13136    // 16
#define SM_FLOATS 13152   // 52608 bytes

__global__ __launch_bounds__(256, 4) void attn_kernel(
    const float* __restrict__ v,
    const float* __restrict__ vs_w,
    float* __restrict__ out,        // [BH,256,64]
    float* __restrict__ attn_out)   // [BH,256,256]
{
    extern __shared__ float sm[];
    uint32_t* kp_u  = (uint32_t*)sm + SM_KP;
    uint32_t* w2h_s = (uint32_t*)sm + SM_W2H;
    float* s_s  = sm + SM_S;
    float* pmax = sm + SM_PMAX;
    float* psum = sm + SM_PSUM;
    float* m_s  = sm + SM_M;
    float* r_s  = sm + SM_R;

    const int tid  = threadIdx.x;
    const int wid  = tid >> 5;
    const int lane = tid & 31;
    const int bh   = blockIdx.x >> 4;
    const int qt   = blockIdx.x & 15;

    // ---- stage kp tile (f16x2, 8192 words) + w --------------------------
    {
        const uint4* src = (const uint4*)(g_ph + (size_t)(NQROWS + bh * LK_) * 32);
        uint4* dst = (uint4*)kp_u;
#pragma unroll
        for (int i = 0; i < 8; i++) dst[tid + 256 * i] = src[tid + 256 * i];
    }
    if (tid < 32) w2h_s[tid] = cvt_h2(vs_w[2 * tid + 1], vs_w[2 * tid]);
    __syncthreads();

    // ---- main loop -------------------------------------------------------
    const int q    = lane & 15;
    const int kh   = lane >> 4;
    const int kbase = wid * 32 + kh * 16;
    const int qrow = bh * LQ_ + qt * 16 + q;
    float cm = -1e30f;

#pragma unroll 1
    for (int h = 0; h < 2; h++) {
        uint32_t qph[16], wh[16];
        {
            const uint4* qs = (const uint4*)(g_ph + (size_t)qrow * 32 + h * 16);
#pragma unroll
            for (int j = 0; j < 4; j++) {
                uint4 t = qs[j];
                qph[4*j] = t.x; qph[4*j+1] = t.y; qph[4*j+2] = t.z; qph[4*j+3] = t.w;
            }
        }
#pragma unroll
        for (int j = 0; j < 16; j++) wh[j] = w2h_s[h * 16 + j];

#pragma unroll 1
        for (int kk = 0; kk < 16; kk++) {
            const int k = kbase + kk;
            const uint4* kr = (const uint4*)(kp_u + k * 32 + h * 16);
            float part = 0.f;
#pragma unroll
            for (int c = 0; c < 2; c++) {
                uint4 a = kr[2*c], b = kr[2*c+1];
                uint32_t kw0 = a.x, kw1 = a.y, kw2 = a.z, kw3 = a.w;
                uint32_t kw4 = b.x, kw5 = b.y, kw6 = b.z, kw7 = b.w;
                uint32_t h0 = 0, h1 = 0;
                h0 = hfma2(tanh2(hadd2(qph[8*c+0], kw0)), wh[8*c+0], h0);
                h1 = hfma2(tanh2(hadd2(qph[8*c+1], kw1)), wh[8*c+1], h1);
                h0 = hfma2(tanh2(hadd2(qph[8*c+2], kw2)), wh[8*c+2], h0);
                h1 = hfma2(tanh2(hadd2(qph[8*c+3], kw3)), wh[8*c+3], h1);
                h0 = hfma2(tanh2(hadd2(qph[8*c+4], kw4)), wh[8*c+4], h0);
                h1 = hfma2(tanh2(hadd2(qph[8*c+5], kw5)), wh[8*c+5], h1);
                h0 = hfma2(tanh2(hadd2(qph[8*c+6], kw6)), wh[8*c+6], h0);
                h1 = hfma2(tanh2(hadd2(qph[8*c+7], kw7)), wh[8*c+7], h1);
                float f0, f1, f2, f3;
                h2tof(h0, f0, f1); h2tof(h1, f2, f3);
                part += (f0 + f1) + (f2 + f3);
            }
            if (h == 0) {
                s_s[k * 17 + q] = part;
            } else {
                const float sc = s_s[k * 17 + q] + part;
                s_s[k * 17 + q] = sc;
                cm = fmaxf(cm, sc);
            }
        }
    }
    pmax[q * 17 + wid * 2 + kh] = cm;
    __syncthreads();

    // ---- stage v as f16x2 (overwrites kp) + reduce row max ---------------
    if (tid < 16) {
        float m = pmax[tid * 17];
#pragma unroll
        for (int i = 1; i < 16; i++) m = fmaxf(m, pmax[tid * 17 + i]);
        m_s[tid] = m;
    }
    {
        const float4* vsrc = (const float4*)(v + (size_t)bh * (LK_ * DK_));
#pragma unroll
        for (int i = 0; i < 16; i++) {
            const int idx = tid + 256 * i;          // float4 index, 0..4095
            float4 t = vsrc[idx];
            uint32_t w0 = cvt_h2(t.y, t.x);
            uint32_t w1 = cvt_h2(t.w, t.z);
            *(uint2*)(kp_u + idx * 2) = make_uint2(w0, w1);
        }
    }
    __syncthreads();

    // ---- exp pass --------------------------------------------------------
    {
        const int qe = tid & 15;
        const int ks = tid >> 4;
        const float m = m_s[qe];
        float s = 0.f;
#pragma unroll 4
        for (int kk = 0; kk < 16; kk++) {
            const int k = ks * 16 + kk;
            const float e = ex2_fast((s_s[k * 17 + qe] - m) * LOG2E);
            s_s[k * 17 + qe] = e;
            s += e;
        }
        psum[qe * 17 + ks] = s;
    }
    __syncthreads();
    if (tid < 16) {
        float l = psum[tid * 17];
#pragma unroll
        for (int i = 1; i < 16; i++) l += psum[tid * 17 + i];
        r_s[tid] = 1.0f / l;
    }
    __syncthreads();

    // ---- write attn (coalesced, normalized) ------------------------------
    {
        float* ab = attn_out + (size_t)(bh * LQ_ + qt * 16) * LK_;
#pragma unroll 4
        for (int i = 0; i < 16; i++)
            ab[i * LK_ + tid] = s_s[tid * 17 + i] * r_s[i];
    }

    // ---- epilogue: out[q][d] = (sum_k e[q][k]*v[k][d]) * r[q] ------------
    // thread: q = tid>>4, words jv,jv+1 -> d0 = (tid&15)*4 .. +3
    {
        const int qo = tid >> 4;
        const int jv = (tid & 15) * 2;
        ull acc01 = 0, acc23 = 0;
#pragma unroll 2
        for (int kb = 0; kb < 64; kb++) {
            uint32_t h0 = 0, h1 = 0;
#pragma unroll
            for (int kk = 0; kk < 4; kk++) {
                const int k = kb * 4 + kk;
                const float p = s_s[k * 17 + qo];
                const uint32_t ph = cvt_h2(p, p);
                uint2 vw = *(const uint2*)(kp_u + k * 32 + jv);
                h0 = hfma2(ph, vw.x, h0);
                h1 = hfma2(ph, vw.y, h1);
            }
            float f0, f1, f2, f3;
            h2tof(h0, f0, f1); h2tof(h1, f2, f3);
            acc01 = add2(acc01, pk(f0, f1));
            acc23 = add2(acc23, pk(f2, f3));
        }
        const float r = r_s[qo];
        float o0, o1, o2, o3;
        upk(acc01, o0, o1); upk(acc23, o2, o3);
        float* ob = out + (size_t)(bh * LQ_ + qt * 16 + qo) * DK_ + (tid & 15) * 4;
        *(float4*)ob = make_float4(o0 * r, o1 * r, o2 * r, o3 * r);
    }
}

// ---------------------------------------------------------------------------
extern "C" void kernel_launch(void* const* d_in, const int* in_sizes, int n_in,
                              void* d_out, int out_size)
{
    const float* q    = (const float*)d_in[0];
    const float* k    = (const float*)d_in[1];
    const float* v    = (const float*)d_in[2];
    const float* Wq_w = (const float*)d_in[3];
    const float* Wq_b = (const float*)d_in[4];
    const float* Wk_w = (const float*)d_in[5];
    const float* Wk_b = (const float*)d_in[6];
    const float* vs_w = (const float*)d_in[7];
    // vs_b (d_in[8]) is softmax-invariant: unused.

    float* out  = (float*)d_out;                            // [B,H,LQ,DK]
    float* attn = (float*)d_out + (size_t)BH_ * LQ_ * DK_;  // [B,H,LQ,LK]

    const int smem_bytes = SM_FLOATS * 4;
    cudaFuncSetAttribute(attn_kernel, cudaFuncAttributeMaxDynamicSharedMemorySize,
                         smem_bytes);

    proj_kernel<<<512, 256>>>(q, k, Wq_w, Wq_b, Wk_w, Wk_b);
    attn_kernel<<<512, 256, smem_bytes>>>(v, vs_w, out, attn);
}

// round 7
// speedup vs baseline: 1.2148x; 1.0574x over previous
#include <cuda_runtime.h>
#include <cuda_bf16.h>
#include <cstdint>

#define B_  4
#define H_  8
#define LQ_ 256
#define LK_ 256
#define DK_ 64
#define BH_ (B_*H_)                 // 32
#define NQROWS (BH_*LQ_)            // 8192
#define NKROWS (BH_*LK_)            // 8192
#define LOG2E 1.4426950408889634f

typedef unsigned long long ull;

// Projected q,k as f16x2 words: row r (0..16383), 32 words (64 dims).
__device__ uint32_t g_ph[(NQROWS + NKROWS) * 32];   // 2 MB

// ---------------- packed-math helpers -------------------------------------
__device__ __forceinline__ ull pk(float lo, float hi) {
    ull r; asm("mov.b64 %0,{%1,%2};" : "=l"(r) : "f"(lo), "f"(hi)); return r;
}
__device__ __forceinline__ void upk(ull v, float& lo, float& hi) {
    asm("mov.b64 {%0,%1},%2;" : "=f"(lo), "=f"(hi) : "l"(v));
}
__device__ __forceinline__ ull fma2(ull a, ull b, ull c) {
    ull r; asm("fma.rn.f32x2 %0,%1,%2,%3;" : "=l"(r) : "l"(a), "l"(b), "l"(c)); return r;
}
// f16x2 pack: first PTX operand -> HIGH half
__device__ __forceinline__ uint32_t cvt_h2(float hi, float lo) {
    uint32_t r; asm("cvt.rn.f16x2.f32 %0,%1,%2;" : "=r"(r) : "f"(hi), "f"(lo)); return r;
}
__device__ __forceinline__ uint32_t hadd2(uint32_t a, uint32_t b) {
    uint32_t r; asm("add.rn.f16x2 %0,%1,%2;" : "=r"(r) : "r"(a), "r"(b)); return r;
}
__device__ __forceinline__ uint32_t hfma2(uint32_t a, uint32_t b, uint32_t c) {
    uint32_t r; asm("fma.rn.f16x2 %0,%1,%2,%3;" : "=r"(r) : "r"(a), "r"(b), "r"(c)); return r;
}
__device__ __forceinline__ uint32_t tanh2(uint32_t x) {
    uint32_t y; asm("tanh.approx.f16x2 %0,%1;" : "=r"(y) : "r"(x)); return y;
}
__device__ __forceinline__ void h2tof(uint32_t h, float& lo, float& hi) {
    asm("{.reg .b16 l,h; mov.b32 {l,h},%2; cvt.f32.f16 %0,l; cvt.f32.f16 %1,h;}"
        : "=f"(lo), "=f"(hi) : "r"(h));
}
__device__ __forceinline__ float ex2_fast(float x) {
    float y; asm("ex2.approx.f32 %0,%1;" : "=f"(y) : "f"(x)); return y;
}
__device__ __forceinline__ uint32_t smem_u32(const void* p) {
    return (uint32_t)__cvta_generic_to_shared(p);
}

// ---------------------------------------------------------------------------
// Kernel 1: projections -> f16x2. grid 512 x 256 thr, 32 rows/CTA.
// ---------------------------------------------------------------------------
__global__ __launch_bounds__(256) void proj_kernel(
    const float* __restrict__ q, const float* __restrict__ k,
    const float* __restrict__ Wq, const float* __restrict__ bq,
    const float* __restrict__ Wk, const float* __restrict__ bk)
{
    __shared__ float wt[64 * 68];     // wt[d*68+e] = W[e][d]
    __shared__ float xs[32 * 64];
    __shared__ float bs[64];
    const int tid = threadIdx.x;
    const bool isK = (blockIdx.x >= 256);
    const float* W    = isK ? Wk : Wq;
    const float* bias = isK ? bk : bq;
    const float* src  = isK ? k : q;
    const int rowbase = (blockIdx.x & 255) * 32;

    for (int i = tid; i < 4096; i += 256)
        wt[(i & 63) * 68 + (i >> 6)] = W[i];
    if (tid < 64) bs[tid] = bias[tid];
    {
        const float4* s4 = (const float4*)(src + rowbase * 64);
        ((float4*)xs)[tid]       = s4[tid];
        ((float4*)xs)[tid + 256] = s4[tid + 256];
    }
    __syncthreads();

    const int r  = tid >> 3;
    const int e0 = (tid & 7) * 8;
    ull acc[4];
#pragma unroll
    for (int j = 0; j < 4; j++) acc[j] = pk(bs[e0 + 2*j], bs[e0 + 2*j + 1]);

#pragma unroll 8
    for (int d = 0; d < 64; d++) {
        const float xd = xs[r * 64 + d];
        const ull xx = pk(xd, xd);
        const float4 wA = *(const float4*)(wt + d * 68 + e0);
        const float4 wB = *(const float4*)(wt + d * 68 + e0 + 4);
        acc[0] = fma2(xx, pk(wA.x, wA.y), acc[0]);
        acc[1] = fma2(xx, pk(wA.z, wA.w), acc[1]);
        acc[2] = fma2(xx, pk(wB.x, wB.y), acc[2]);
        acc[3] = fma2(xx, pk(wB.z, wB.w), acc[3]);
    }

    uint32_t h[4];
#pragma unroll
    for (int j = 0; j < 4; j++) {
        float lo, hi; upk(acc[j], lo, hi);
        h[j] = cvt_h2(hi, lo);
    }
    const int row = (isK ? NQROWS : 0) + rowbase + r;
    *(uint4*)(g_ph + (size_t)row * 32 + (tid & 7) * 4) =
        make_uint4(h[0], h[1], h[2], h[3]);
}

// ---------------------------------------------------------------------------
// Kernel 2: fused additive attention.
// grid = 512 CTAs (32 bh x 16 q-tiles of 16 rows), 256 thr, 4 CTAs/SM.
// f16x2 tanh main loop; softmax in regs; p -> f16 smem (pitch 264 f16);
// v -> f16 smem (pitch 72 f16, 144B = 16B-aligned rows for ldmatrix);
// epilogue = HMMA m16n8k16 f32-accum GEMM.
// ---------------------------------------------------------------------------
// smem layout (u32 word indices)
#define SM_KV    0        // 9216 (kp f16x2 pitch 32 uses 8192; v f16 pitch 36w uses 9216)
#define SM_W2H   9216     // 32
#define SM_S     9248     // 4352 f32 scores pitch 17; later p_h f16 pitch 264
#define SM_PMAX  13600    // 16 x 17
#define SM_PSUM  13872    // 16 x 17
#define SM_M     14144    // 16
#define SM_R     14160    // 16
#define SM_WORDS 14176    // 56704 bytes

#define P_PITCH_W 132     // p_h pitch in u32 words (264 f16, 528B: 16B-aligned)
#define V_PITCH_W 36      // v_h pitch in u32 words (72 f16, 144B: 16B-aligned)

__global__ __launch_bounds__(256, 4) void attn_kernel(
    const float* __restrict__ v,
    const float* __restrict__ vs_w,
    float* __restrict__ out,        // [BH,256,64]
    float* __restrict__ attn_out)   // [BH,256,256]
{
    extern __shared__ float sm[];
    uint32_t* kv_u  = (uint32_t*)sm + SM_KV;
    uint32_t* w2h_s = (uint32_t*)sm + SM_W2H;
    float*    s_s   = sm + SM_S;
    uint32_t* ph_u  = (uint32_t*)sm + SM_S;   // overlays s_s after scores die
    float* pmax = sm + SM_PMAX;
    float* psum = sm + SM_PSUM;
    float* m_s  = sm + SM_M;
    float* r_s  = sm + SM_R;

    const int tid  = threadIdx.x;
    const int wid  = tid >> 5;
    const int lane = tid & 31;
    const int bh   = blockIdx.x >> 4;
    const int qt   = blockIdx.x & 15;

    // ---- phase 0: stage kp (f16x2, pitch 32 words) + w --------------------
    {
        const uint4* src = (const uint4*)(g_ph + (size_t)(NQROWS + bh * LK_) * 32);
        uint4* dst = (uint4*)kv_u;
#pragma unroll
        for (int i = 0; i < 8; i++) dst[tid + 256 * i] = src[tid + 256 * i];
    }
    if (tid < 32) w2h_s[tid] = cvt_h2(vs_w[2 * tid + 1], vs_w[2 * tid]);
    __syncthreads();

    // ---- phase 1: scores ---------------------------------------------------
    const int q    = lane & 15;
    const int kh   = lane >> 4;
    const int kbase = wid * 32 + kh * 16;
    const int qrow = bh * LQ_ + qt * 16 + q;
    float cm = -1e30f;

#pragma unroll 1
    for (int h = 0; h < 2; h++) {
        uint32_t qph[16], wh[16];
        {
            const uint4* qs = (const uint4*)(g_ph + (size_t)qrow * 32 + h * 16);
#pragma unroll
            for (int j = 0; j < 4; j++) {
                uint4 t = qs[j];
                qph[4*j] = t.x; qph[4*j+1] = t.y; qph[4*j+2] = t.z; qph[4*j+3] = t.w;
            }
        }
#pragma unroll
        for (int j = 0; j < 16; j++) wh[j] = w2h_s[h * 16 + j];

        const uint4* kr = (const uint4*)(kv_u + kbase * 32 + h * 16);
        uint4 ca = kr[0], cb = kr[1];
#pragma unroll 1
        for (int kk = 0; kk < 16; kk++) {
            // prefetch next k row (software pipeline)
            uint4 na, nb;
            if (kk < 15) { na = kr[(kk + 1) * 8]; nb = kr[(kk + 1) * 8 + 1]; }
            const int k = kbase + kk;
            uint32_t h0 = 0, h1 = 0;
            h0 = hfma2(tanh2(hadd2(qph[0], ca.x)), wh[0], h0);
            h1 = hfma2(tanh2(hadd2(qph[1], ca.y)), wh[1], h1);
            h0 = hfma2(tanh2(hadd2(qph[2], ca.z)), wh[2], h0);
            h1 = hfma2(tanh2(hadd2(qph[3], ca.w)), wh[3], h1);
            h0 = hfma2(tanh2(hadd2(qph[4], cb.x)), wh[4], h0);
            h1 = hfma2(tanh2(hadd2(qph[5], cb.y)), wh[5], h1);
            h0 = hfma2(tanh2(hadd2(qph[6], cb.z)), wh[6], h0);
            h1 = hfma2(tanh2(hadd2(qph[7], cb.w)), wh[7], h1);
            float f0, f1, f2, f3;
            h2tof(h0, f0, f1); h2tof(h1, f2, f3);
            float part = (f0 + f1) + (f2 + f3);

            {
                uint4 c2 = kr[kk * 8 + 2], c3 = kr[kk * 8 + 3];
                uint32_t g0 = 0, g1 = 0;
                g0 = hfma2(tanh2(hadd2(qph[8],  c2.x)), wh[8],  g0);
                g1 = hfma2(tanh2(hadd2(qph[9],  c2.y)), wh[9],  g1);
                g0 = hfma2(tanh2(hadd2(qph[10], c2.z)), wh[10], g0);
                g1 = hfma2(tanh2(hadd2(qph[11], c2.w)), wh[11], g1);
                g0 = hfma2(tanh2(hadd2(qph[12], c3.x)), wh[12], g0);
                g1 = hfma2(tanh2(hadd2(qph[13], c3.y)), wh[13], g1);
                g0 = hfma2(tanh2(hadd2(qph[14], c3.z)), wh[14], g0);
                g1 = hfma2(tanh2(hadd2(qph[15], c3.w)), wh[15], g1);
                h2tof(g0, f0, f1); h2tof(g1, f2, f3);
                part += (f0 + f1) + (f2 + f3);
            }

            if (h == 0) {
                s_s[k * 17 + q] = part;
            } else {
                const float sc = s_s[k * 17 + q] + part;
                s_s[k * 17 + q] = sc;
                cm = fmaxf(cm, sc);
            }
            ca = na; cb = nb;
        }
    }
    pmax[q * 17 + wid * 2 + kh] = cm;
    __syncthreads();

    // ---- phase 2: row max + stage v as f16 (pitch 72 f16, overwrites kp) --
    if (tid < 16) {
        float m = pmax[tid * 17];
#pragma unroll
        for (int i = 1; i < 16; i++) m = fmaxf(m, pmax[tid * 17 + i]);
        m_s[tid] = m;
    }
    {
        const float4* vsrc = (const float4*)(v + (size_t)bh * (LK_ * DK_));
#pragma unroll
        for (int i = 0; i < 16; i++) {
            const int idx = tid + 256 * i;           // 0..4095; k=idx>>4, c=idx&15
            float4 t = vsrc[idx];
            const int kk2 = idx >> 4, c = idx & 15;
            uint32_t w0 = cvt_h2(t.y, t.x);
            uint32_t w1 = cvt_h2(t.w, t.z);
            *(uint2*)(kv_u + kk2 * V_PITCH_W + 2 * c) = make_uint2(w0, w1);
        }
    }
    __syncthreads();

    // ---- phase 3: exp into registers, partial sums -------------------------
    const int qe = tid & 15;
    const int ks = tid >> 4;
    float e[16];
    {
        const float m = m_s[qe];
        float s = 0.f;
#pragma unroll
        for (int kk = 0; kk < 16; kk++) {
            const int k = ks * 16 + kk;
            const float ev = ex2_fast((s_s[k * 17 + qe] - m) * LOG2E);
            e[kk] = ev;
            s += ev;
        }
        psum[qe * 17 + ks] = s;
    }
    __syncthreads();
    if (tid < 16) {
        float l = psum[tid * 17];
#pragma unroll
        for (int i = 1; i < 16; i++) l += psum[tid * 17 + i];
        r_s[tid] = 1.0f / l;
    }
    __syncthreads();

    // ---- phase 4: write attn (from regs) + p_h f16 (overlays s_s) ---------
    {
        const float r = r_s[qe];
        float4* ab = (float4*)(attn_out + (size_t)(bh * LQ_ + qt * 16 + qe) * LK_
                               + ks * 16);
#pragma unroll
        for (int j = 0; j < 4; j++)
            ab[j] = make_float4(e[4*j] * r, e[4*j+1] * r, e[4*j+2] * r, e[4*j+3] * r);
#pragma unroll
        for (int j = 0; j < 8; j++)
            ph_u[qe * P_PITCH_W + ks * 8 + j] = cvt_h2(e[2*j+1] * r, e[2*j] * r);
    }
    __syncthreads();

    // ---- phase 5: epilogue GEMM out[16q x 64d] = p[16x256] @ v[256x64] ----
    // warp wid -> d-tile [8*wid, 8*wid+8)
    {
        const int d0 = wid * 8;
        float c0 = 0.f, c1 = 0.f, c2 = 0.f, c3 = 0.f;
        const uint32_t pa_base = smem_u32(ph_u) + ((lane & 15) * P_PITCH_W) * 4;
        const uint32_t vb_base = smem_u32(kv_u) + ((lane & 15) * V_PITCH_W + (d0 >> 1)) * 4;
#pragma unroll
        for (int kb = 0; kb < 16; kb++) {
            uint32_t a0, a1, a2, a3, b0, b1;
            const uint32_t pa = pa_base + (kb * 8 + (lane >> 4) * 4) * 4;
            asm volatile("ldmatrix.sync.aligned.m8n8.x4.shared.b16 {%0,%1,%2,%3}, [%4];"
                         : "=r"(a0), "=r"(a1), "=r"(a2), "=r"(a3) : "r"(pa));
            const uint32_t vb = vb_base + (kb * 16 * V_PITCH_W) * 4;
            asm volatile("ldmatrix.sync.aligned.m8n8.x2.trans.shared.b16 {%0,%1}, [%2];"
                         : "=r"(b0), "=r"(b1) : "r"(vb));
            asm volatile("mma.sync.aligned.m16n8k16.row.col.f32.f16.f16.f32 "
                         "{%0,%1,%2,%3},{%4,%5,%6,%7},{%8,%9},{%0,%1,%2,%3};"
                         : "+f"(c0), "+f"(c1), "+f"(c2), "+f"(c3)
                         : "r"(a0), "r"(a1), "r"(a2), "r"(a3), "r"(b0), "r"(b1));
        }
        const int qr = lane >> 2;
        const int dc = d0 + 2 * (lane & 3);
        float* ob = out + (size_t)(bh * LQ_ + qt * 16) * DK_;
        *(float2*)(ob + qr * DK_ + dc)       = make_float2(c0, c1);
        *(float2*)(ob + (qr + 8) * DK_ + dc) = make_float2(c2, c3);
    }
}

// ---------------------------------------------------------------------------
extern "C" void kernel_launch(void* const* d_in, const int* in_sizes, int n_in,
                              void* d_out, int out_size)
{
    const float* q    = (const float*)d_in[0];
    const float* k    = (const float*)d_in[1];
    const float* v    = (const float*)d_in[2];
    const float* Wq_w = (const float*)d_in[3];
    const float* Wq_b = (const float*)d_in[4];
    const float* Wk_w = (const float*)d_in[5];
    const float* Wk_b = (const float*)d_in[6];
    const float* vs_w = (const float*)d_in[7];
    // vs_b (d_in[8]) is softmax-invariant: unused.

    float* out  = (float*)d_out;                            // [B,H,LQ,DK]
    float* attn = (float*)d_out + (size_t)BH_ * LQ_ * DK_;  // [B,H,LQ,LK]

    const int smem_bytes = SM_WORDS * 4;
    cudaFuncSetAttribute(attn_kernel, cudaFuncAttributeMaxDynamicSharedMemorySize,
                         smem_bytes);

    proj_kernel<<<512, 256>>>(q, k, Wq_w, Wq_b, Wk_w, Wk_b);
    attn_kernel<<<512, 256, smem_bytes>>>(v, vs_w, out, attn);
}

// round 9
// speedup vs baseline: 1.4649x; 1.2059x over previous
#include <cuda_runtime.h>
#include <cuda_bf16.h>
#include <cstdint>

#define B_  4
#define H_  8
#define LQ_ 256
#define LK_ 256
#define DK_ 64
#define BH_ (B_*H_)                 // 32
#define NQROWS (BH_*LQ_)            // 8192
#define NKROWS (BH_*LK_)            // 8192
#define LOG2E 1.4426950408889634f

typedef unsigned long long ull;

// Projected q,k as f16x2 words: row r (0..16383), 32 words (64 dims).
__device__ uint32_t g_ph[(NQROWS + NKROWS) * 32];   // 2 MB

// ---------------- packed-math helpers -------------------------------------
// f16x2 pack: first PTX operand -> HIGH half
__device__ __forceinline__ uint32_t cvt_h2(float hi, float lo) {
    uint32_t r; asm("cvt.rn.f16x2.f32 %0,%1,%2;" : "=r"(r) : "f"(hi), "f"(lo)); return r;
}
__device__ __forceinline__ uint32_t hadd2(uint32_t a, uint32_t b) {
    uint32_t r; asm("add.rn.f16x2 %0,%1,%2;" : "=r"(r) : "r"(a), "r"(b)); return r;
}
__device__ __forceinline__ uint32_t hfma2(uint32_t a, uint32_t b, uint32_t c) {
    uint32_t r; asm("fma.rn.f16x2 %0,%1,%2,%3;" : "=r"(r) : "r"(a), "r"(b), "r"(c)); return r;
}
__device__ __forceinline__ uint32_t tanh2(uint32_t x) {
    uint32_t y; asm("tanh.approx.f16x2 %0,%1;" : "=r"(y) : "r"(x)); return y;
}
__device__ __forceinline__ void h2tof(uint32_t h, float& lo, float& hi) {
    asm("{.reg .b16 l,h; mov.b32 {l,h},%2; cvt.f32.f16 %0,l; cvt.f32.f16 %1,h;}"
        : "=f"(lo), "=f"(hi) : "r"(h));
}
__device__ __forceinline__ float ex2_fast(float x) {
    float y; asm("ex2.approx.f32 %0,%1;" : "=f"(y) : "f"(x)); return y;
}
__device__ __forceinline__ uint32_t smem_u32(const void* p) {
    return (uint32_t)__cvta_generic_to_shared(p);
}

// ---------------------------------------------------------------------------
// Kernel 1: projections via HMMA. grid 256 CTAs x 128 thr (4 warps).
// CTA: 64 rows of q (cta<128) or k (cta>=128). Warp: 16-row tile.
// C[r][e] = sum_d x[r][d] * W[e][d] + b[e]  -> f16x2 words in g_ph.
// A = x f16 [row][d] pitch 36 words; B = W^T f16 [d][e] pitch 36 words.
// ---------------------------------------------------------------------------
__global__ __launch_bounds__(128) void proj_kernel(
    const float* __restrict__ q, const float* __restrict__ k,
    const float* __restrict__ Wq, const float* __restrict__ bq,
    const float* __restrict__ Wk, const float* __restrict__ bk)
{
    __shared__ uint32_t xs[64 * 36];   // x f16, 64 rows, pitch 72 f16
    __shared__ uint32_t ws[64 * 36];   // W^T f16: row d, cols e
    __shared__ float bs[64];
    const int tid  = threadIdx.x;
    const int wid  = tid >> 5;
    const int lane = tid & 31;
    const bool isK = (blockIdx.x >= 128);
    const float* W    = isK ? Wk : Wq;
    const float* bias = isK ? bk : bq;
    const int rowbase = (blockIdx.x & 127) * 64;
    const float* src  = (isK ? k : q) + (size_t)rowbase * 64;

    // stage x (64 rows x 32 words) as f16
    for (int i = tid; i < 2048; i += 128) {
        const int row = i >> 5, j = i & 31;
        float2 t = *(const float2*)(src + row * 64 + 2 * j);
        xs[row * 36 + j] = cvt_h2(t.y, t.x);
    }
    // stage W^T: word (d, j) = (W[2j][d], W[2j+1][d])
    for (int i = tid; i < 2048; i += 128) {
        const int d = i >> 5, j = i & 31;
        ws[d * 36 + j] = cvt_h2(W[(2 * j + 1) * 64 + d], W[(2 * j) * 64 + d]);
    }
    if (tid < 64) bs[tid] = bias[tid];
    __syncthreads();

    // A fragments: 4 k-steps of this warp's 16 rows
    uint32_t a[4][4];
    {
        const uint32_t abase = smem_u32(xs) + ((wid * 16 + (lane & 15)) * 36) * 4;
#pragma unroll
        for (int ks = 0; ks < 4; ks++) {
            const uint32_t pa = abase + (ks * 8 + (lane >> 4) * 4) * 4;
            asm volatile("ldmatrix.sync.aligned.m8n8.x4.shared.b16 {%0,%1,%2,%3}, [%4];"
                         : "=r"(a[ks][0]), "=r"(a[ks][1]), "=r"(a[ks][2]), "=r"(a[ks][3])
                         : "r"(pa));
        }
    }

    const int qr = lane >> 2;
    const int cb = 2 * (lane & 3);
    const int rowg = (isK ? NQROWS : 0) + rowbase + wid * 16 + qr;
#pragma unroll
    for (int n = 0; n < 8; n++) {
        float c0 = 0.f, c1 = 0.f, c2 = 0.f, c3 = 0.f;
#pragma unroll
        for (int ks = 0; ks < 4; ks++) {
            uint32_t b0, b1;
            const uint32_t vb = smem_u32(ws) + ((ks * 16 + (lane & 15)) * 36 + n * 4) * 4;
            asm volatile("ldmatrix.sync.aligned.m8n8.x2.trans.shared.b16 {%0,%1}, [%2];"
                         : "=r"(b0), "=r"(b1) : "r"(vb));
            asm volatile("mma.sync.aligned.m16n8k16.row.col.f32.f16.f16.f32 "
                         "{%0,%1,%2,%3},{%4,%5,%6,%7},{%8,%9},{%0,%1,%2,%3};"
                         : "+f"(c0), "+f"(c1), "+f"(c2), "+f"(c3)
                         : "r"(a[ks][0]), "r"(a[ks][1]), "r"(a[ks][2]), "r"(a[ks][3]),
                           "r"(b0), "r"(b1));
        }
        const int col = n * 8 + cb;
        const float blo = bs[col], bhi = bs[col + 1];
        g_ph[(size_t)rowg * 32 + n * 4 + (lane & 3)] =
            cvt_h2(c1 + bhi, c0 + blo);
        g_ph[(size_t)(rowg + 8) * 32 + n * 4 + (lane & 3)] =
            cvt_h2(c3 + bhi, c2 + blo);
    }
}

// ---------------------------------------------------------------------------
// Kernel 2: fused additive attention.
// grid = 512 CTAs (32 bh x 16 q-tiles of 16 rows), 256 thr, 4 CTAs/SM.
// f16x2 tanh main loop (single flush/iter); softmax in regs;
// p -> f16 smem (pitch 264 f16); v -> f16 smem (pitch 72 f16);
// epilogue = HMMA m16n8k16 f32-accum GEMM.
// ---------------------------------------------------------------------------
// smem layout (u32 word indices)
#define SM_KV    0        // 9216
#define SM_W2H   9216     // 32
#define SM_S     9248     // 4352 f32 scores pitch 17; later p_h f16 pitch 264
#define SM_PMAX  13600    // 16 x 17
#define SM_PSUM  13872    // 16 x 17
#define SM_M     14144    // 16
#define SM_R     14160    // 16
#define SM_WORDS 14176    // 56704 bytes

#define P_PITCH_W 132     // p_h pitch in u32 words (264 f16, 528B)
#define V_PITCH_W 36      // v_h pitch in u32 words (72 f16, 144B)

__global__ __launch_bounds__(256, 4) void attn_kernel(
    const float* __restrict__ v,
    const float* __restrict__ vs_w,
    float* __restrict__ out,        // [BH,256,64]
    float* __restrict__ attn_out)   // [BH,256,256]
{
    extern __shared__ float sm[];
    uint32_t* kv_u  = (uint32_t*)sm + SM_KV;
    uint32_t* w2h_s = (uint32_t*)sm + SM_W2H;
    float*    s_s   = sm + SM_S;
    uint32_t* ph_u  = (uint32_t*)sm + SM_S;   // overlays s_s after scores die
    float* pmax = sm + SM_PMAX;
    float* psum = sm + SM_PSUM;
    float* m_s  = sm + SM_M;
    float* r_s  = sm + SM_R;

    const int tid  = threadIdx.x;
    const int wid  = tid >> 5;
    const int lane = tid & 31;
    const int bh   = blockIdx.x >> 4;
    const int qt   = blockIdx.x & 15;

    // ---- phase 0: stage kp (f16x2, pitch 32 words) + w --------------------
    {
        const uint4* src = (const uint4*)(g_ph + (size_t)(NQROWS + bh * LK_) * 32);
        uint4* dst = (uint4*)kv_u;
#pragma unroll
        for (int i = 0; i < 8; i++) dst[tid + 256 * i] = src[tid + 256 * i];
    }
    if (tid < 32) w2h_s[tid] = cvt_h2(vs_w[2 * tid + 1], vs_w[2 * tid]);
    __syncthreads();

    // ---- phase 1: scores ---------------------------------------------------
    const int q    = lane & 15;
    const int kh   = lane >> 4;
    const int kbase = wid * 32 + kh * 16;
    const int qrow = bh * LQ_ + qt * 16 + q;
    float cm = -1e30f;

#pragma unroll 1
    for (int h = 0; h < 2; h++) {
        uint32_t qph[16], wh[16];
        {
            const uint4* qs = (const uint4*)(g_ph + (size_t)qrow * 32 + h * 16);
#pragma unroll
            for (int j = 0; j < 4; j++) {
                uint4 t = qs[j];
                qph[4*j] = t.x; qph[4*j+1] = t.y; qph[4*j+2] = t.z; qph[4*j+3] = t.w;
            }
        }
#pragma unroll
        for (int j = 0; j < 16; j++) wh[j] = w2h_s[h * 16 + j];

        const uint4* kr = (const uint4*)(kv_u + kbase * 32 + h * 16);
        uint4 ca = kr[0], cb = kr[1];
#pragma unroll 1
        for (int kk = 0; kk < 16; kk++) {
            uint4 na, nb;
            if (kk < 15) { na = kr[(kk + 1) * 8]; nb = kr[(kk + 1) * 8 + 1]; }
            const int k = kbase + kk;
            uint32_t h0 = 0, h1 = 0, g0 = 0, g1 = 0;
            h0 = hfma2(tanh2(hadd2(qph[0], ca.x)), wh[0], h0);
            h1 = hfma2(tanh2(hadd2(qph[1], ca.y)), wh[1], h1);
            h0 = hfma2(tanh2(hadd2(qph[2], ca.z)), wh[2], h0);
            h1 = hfma2(tanh2(hadd2(qph[3], ca.w)), wh[3], h1);
            h0 = hfma2(tanh2(hadd2(qph[4], cb.x)), wh[4], h0);
            h1 = hfma2(tanh2(hadd2(qph[5], cb.y)), wh[5], h1);
            h0 = hfma2(tanh2(hadd2(qph[6], cb.z)), wh[6], h0);
            h1 = hfma2(tanh2(hadd2(qph[7], cb.w)), wh[7], h1);
            {
                uint4 c2 = kr[kk * 8 + 2], c3 = kr[kk * 8 + 3];
                g0 = hfma2(tanh2(hadd2(qph[8],  c2.x)), wh[8],  g0);
                g1 = hfma2(tanh2(hadd2(qph[9],  c2.y)), wh[9],  g1);
                g0 = hfma2(tanh2(hadd2(qph[10], c2.z)), wh[10], g0);
                g1 = hfma2(tanh2(hadd2(qph[11], c2.w)), wh[11], g1);
                g0 = hfma2(tanh2(hadd2(qph[12], c3.x)), wh[12], g0);
                g1 = hfma2(tanh2(hadd2(qph[13], c3.y)), wh[13], g1);
                g0 = hfma2(tanh2(hadd2(qph[14], c3.z)), wh[14], g0);
                g1 = hfma2(tanh2(hadd2(qph[15], c3.w)), wh[15], g1);
            }
            float f0, f1, f2, f3, f4, f5, f6, f7;
            h2tof(h0, f0, f1); h2tof(h1, f2, f3);
            h2tof(g0, f4, f5); h2tof(g1, f6, f7);
            const float part = ((f0 + f1) + (f2 + f3)) + ((f4 + f5) + (f6 + f7));

            if (h == 0) {
                s_s[k * 17 + q] = part;
            } else {
                const float sc = s_s[k * 17 + q] + part;
                s_s[k * 17 + q] = sc;
                cm = fmaxf(cm, sc);
            }
            ca = na; cb = nb;
        }
    }
    pmax[q * 17 + wid * 2 + kh] = cm;
    __syncthreads();

    // ---- phase 2: row max + stage v as f16 (pitch 72 f16, overwrites kp) --
    if (tid < 16) {
        float m = pmax[tid * 17];
#pragma unroll
        for (int i = 1; i < 16; i++) m = fmaxf(m, pmax[tid * 17 + i]);
        m_s[tid] = m;
    }
    {
        const float4* vsrc = (const float4*)(v + (size_t)bh * (LK_ * DK_));
#pragma unroll
        for (int i = 0; i < 16; i++) {
            const int idx = tid + 256 * i;           // 0..4095; k=idx>>4, c=idx&15
            float4 t = vsrc[idx];
            const int kk2 = idx >> 4, c = idx & 15;
            uint32_t w0 = cvt_h2(t.y, t.x);
            uint32_t w1 = cvt_h2(t.w, t.z);
            *(uint2*)(kv_u + kk2 * V_PITCH_W + 2 * c) = make_uint2(w0, w1);
        }
    }
    __syncthreads();

    // ---- phase 3: exp into registers, partial sums -------------------------
    const int qe = tid & 15;
    const int ks = tid >> 4;
    float e[16];
    {
        const float m = m_s[qe];
        float s = 0.f;
#pragma unroll
        for (int kk = 0; kk < 16; kk++) {
            const int k = ks * 16 + kk;
            const float ev = ex2_fast((s_s[k * 17 + qe] - m) * LOG2E);
            e[kk] = ev;
            s += ev;
        }
        psum[qe * 17 + ks] = s;
    }
    __syncthreads();
    if (tid < 16) {
        float l = psum[tid * 17];
#pragma unroll
        for (int i = 1; i < 16; i++) l += psum[tid * 17 + i];
        r_s[tid] = 1.0f / l;
    }
    __syncthreads();

    // ---- phase 4: write attn (from regs) + p_h f16 (overlays s_s) ---------
    {
        const float r = r_s[qe];
        float4* ab = (float4*)(attn_out + (size_t)(bh * LQ_ + qt * 16 + qe) * LK_
                               + ks * 16);
#pragma unroll
        for (int j = 0; j < 4; j++)
            ab[j] = make_float4(e[4*j] * r, e[4*j+1] * r, e[4*j+2] * r, e[4*j+3] * r);
#pragma unroll
        for (int j = 0; j < 8; j++)
            ph_u[qe * P_PITCH_W + ks * 8 + j] = cvt_h2(e[2*j+1] * r, e[2*j] * r);
    }
    __syncthreads();

    // ---- phase 5: epilogue GEMM out[16q x 64d] = p[16x256] @ v[256x64] ----
    {
        const int d0 = wid * 8;
        float c0 = 0.f, c1 = 0.f, c2 = 0.f, c3 = 0.f;
        const uint32_t pa_base = smem_u32(ph_u) + ((lane & 15) * P_PITCH_W) * 4;
        const uint32_t vb_base = smem_u32(kv_u) + ((lane & 15) * V_PITCH_W + (d0 >> 1)) * 4;
#pragma unroll
        for (int kb = 0; kb < 16; kb++) {
            uint32_t a0, a1, a2, a3, b0, b1;
            const uint32_t pa = pa_base + (kb * 8 + (lane >> 4) * 4) * 4;
            asm volatile("ldmatrix.sync.aligned.m8n8.x4.shared.b16 {%0,%1,%2,%3}, [%4];"
                         : "=r"(a0), "=r"(a1), "=r"(a2), "=r"(a3) : "r"(pa));
            const uint32_t vb = vb_base + (kb * 16 * V_PITCH_W) * 4;
            asm volatile("ldmatrix.sync.aligned.m8n8.x2.trans.shared.b16 {%0,%1}, [%2];"
                         : "=r"(b0), "=r"(b1) : "r"(vb));
            asm volatile("mma.sync.aligned.m16n8k16.row.col.f32.f16.f16.f32 "
                         "{%0,%1,%2,%3},{%4,%5,%6,%7},{%8,%9},{%0,%1,%2,%3};"
                         : "+f"(c0), "+f"(c1), "+f"(c2), "+f"(c3)
                         : "r"(a0), "r"(a1), "r"(a2), "r"(a3), "r"(b0), "r"(b1));
        }
        const int qr = lane >> 2;
        const int dc = d0 + 2 * (lane & 3);
        float* ob = out + (size_t)(bh * LQ_ + qt * 16) * DK_;
        *(float2*)(ob + qr * DK_ + dc)       = make_float2(c0, c1);
        *(float2*)(ob + (qr + 8) * DK_ + dc) = make_float2(c2, c3);
    }
}

// ---------------------------------------------------------------------------
extern "C" void kernel_launch(void* const* d_in, const int* in_sizes, int n_in,
                              void* d_out, int out_size)
{
    const float* q    = (const float*)d_in[0];
    const float* k    = (const float*)d_in[1];
    const float* v    = (const float*)d_in[2];
    const float* Wq_w = (const float*)d_in[3];
    const float* Wq_b = (const float*)d_in[4];
    const float* Wk_w = (const float*)d_in[5];
    const float* Wk_b = (const float*)d_in[6];
    const float* vs_w = (const float*)d_in[7];
    // vs_b (d_in[8]) is softmax-invariant: unused.

    float* out  = (float*)d_out;                            // [B,H,LQ,DK]
    float* attn = (float*)d_out + (size_t)BH_ * LQ_ * DK_;  // [B,H,LQ,LK]

    const int smem_bytes = SM_WORDS * 4;
    cudaFuncSetAttribute(attn_kernel, cudaFuncAttributeMaxDynamicSharedMemorySize,
                         smem_bytes);

    proj_kernel<<<256, 128>>>(q, k, Wq_w, Wq_b, Wk_w, Wk_b);
    attn_kernel<<<512, 256, smem_bytes>>>(v, vs_w, out, attn);
}

// round 10
// speedup vs baseline: 1.4763x; 1.0078x over previous
#include <cuda_runtime.h>
#include <cuda_bf16.h>
#include <cstdint>

#define B_  4
#define H_  8
#define LQ_ 256
#define LK_ 256
#define DK_ 64
#define BH_ (B_*H_)                 // 32
#define NQROWS (BH_*LQ_)            // 8192
#define NKROWS (BH_*LK_)            // 8192
#define LOG2E 1.4426950408889634f

typedef unsigned long long ull;

// Projected q,k as f16x2 words: row r (0..16383), 32 words (64 dims).
__device__ uint32_t g_ph[(NQROWS + NKROWS) * 32];   // 2 MB

// ---------------- packed-math helpers -------------------------------------
// f16x2 pack: first PTX operand -> HIGH half
__device__ __forceinline__ uint32_t cvt_h2(float hi, float lo) {
    uint32_t r; asm("cvt.rn.f16x2.f32 %0,%1,%2;" : "=r"(r) : "f"(hi), "f"(lo)); return r;
}
__device__ __forceinline__ uint32_t hadd2(uint32_t a, uint32_t b) {
    uint32_t r; asm("add.rn.f16x2 %0,%1,%2;" : "=r"(r) : "r"(a), "r"(b)); return r;
}
__device__ __forceinline__ uint32_t hfma2(uint32_t a, uint32_t b, uint32_t c) {
    uint32_t r; asm("fma.rn.f16x2 %0,%1,%2,%3;" : "=r"(r) : "r"(a), "r"(b), "r"(c)); return r;
}
__device__ __forceinline__ uint32_t tanh2(uint32_t x) {
    uint32_t y; asm("tanh.approx.f16x2 %0,%1;" : "=r"(y) : "r"(x)); return y;
}
__device__ __forceinline__ void h2tof(uint32_t h, float& lo, float& hi) {
    asm("{.reg .b16 l,h; mov.b32 {l,h},%2; cvt.f32.f16 %0,l; cvt.f32.f16 %1,h;}"
        : "=f"(lo), "=f"(hi) : "r"(h));
}
__device__ __forceinline__ float ex2_fast(float x) {
    float y; asm("ex2.approx.f32 %0,%1;" : "=f"(y) : "f"(x)); return y;
}
__device__ __forceinline__ uint32_t smem_u32(const void* p) {
    return (uint32_t)__cvta_generic_to_shared(p);
}

// ---------------------------------------------------------------------------
// Kernel 1: projections via HMMA. grid 256 CTAs x 128 thr (4 warps).
// CTA: 64 rows of q (cta<128) or k (cta>=128). Warp: 16-row tile.
// ---------------------------------------------------------------------------
__global__ __launch_bounds__(128) void proj_kernel(
    const float* __restrict__ q, const float* __restrict__ k,
    const float* __restrict__ Wq, const float* __restrict__ bq,
    const float* __restrict__ Wk, const float* __restrict__ bk)
{
    __shared__ uint32_t xs[64 * 36];   // x f16, 64 rows, pitch 72 f16
    __shared__ uint32_t ws[64 * 36];   // W^T f16: row d, cols e
    __shared__ float bs[64];
    const int tid  = threadIdx.x;
    const int wid  = tid >> 5;
    const int lane = tid & 31;
    const bool isK = (blockIdx.x >= 128);
    const float* W    = isK ? Wk : Wq;
    const float* bias = isK ? bk : bq;
    const int rowbase = (blockIdx.x & 127) * 64;
    const float* src  = (isK ? k : q) + (size_t)rowbase * 64;

    for (int i = tid; i < 2048; i += 128) {
        const int row = i >> 5, j = i & 31;
        float2 t = *(const float2*)(src + row * 64 + 2 * j);
        xs[row * 36 + j] = cvt_h2(t.y, t.x);
    }
    for (int i = tid; i < 2048; i += 128) {
        const int d = i >> 5, j = i & 31;
        ws[d * 36 + j] = cvt_h2(W[(2 * j + 1) * 64 + d], W[(2 * j) * 64 + d]);
    }
    if (tid < 64) bs[tid] = bias[tid];
    __syncthreads();

    uint32_t a[4][4];
    {
        const uint32_t abase = smem_u32(xs) + ((wid * 16 + (lane & 15)) * 36) * 4;
#pragma unroll
        for (int ks = 0; ks < 4; ks++) {
            const uint32_t pa = abase + (ks * 8 + (lane >> 4) * 4) * 4;
            asm volatile("ldmatrix.sync.aligned.m8n8.x4.shared.b16 {%0,%1,%2,%3}, [%4];"
                         : "=r"(a[ks][0]), "=r"(a[ks][1]), "=r"(a[ks][2]), "=r"(a[ks][3])
                         : "r"(pa));
        }
    }

    const int qr = lane >> 2;
    const int cb = 2 * (lane & 3);
    const int rowg = (isK ? NQROWS : 0) + rowbase + wid * 16 + qr;
#pragma unroll
    for (int n = 0; n < 8; n++) {
        float c0 = 0.f, c1 = 0.f, c2 = 0.f, c3 = 0.f;
#pragma unroll
        for (int ks = 0; ks < 4; ks++) {
            uint32_t b0, b1;
            const uint32_t vb = smem_u32(ws) + ((ks * 16 + (lane & 15)) * 36 + n * 4) * 4;
            asm volatile("ldmatrix.sync.aligned.m8n8.x2.trans.shared.b16 {%0,%1}, [%2];"
                         : "=r"(b0), "=r"(b1) : "r"(vb));
            asm volatile("mma.sync.aligned.m16n8k16.row.col.f32.f16.f16.f32 "
                         "{%0,%1,%2,%3},{%4,%5,%6,%7},{%8,%9},{%0,%1,%2,%3};"
                         : "+f"(c0), "+f"(c1), "+f"(c2), "+f"(c3)
                         : "r"(a[ks][0]), "r"(a[ks][1]), "r"(a[ks][2]), "r"(a[ks][3]),
                           "r"(b0), "r"(b1));
        }
        const int col = n * 8 + cb;
        const float blo = bs[col], bhi = bs[col + 1];
        g_ph[(size_t)rowg * 32 + n * 4 + (lane & 3)] =
            cvt_h2(c1 + bhi, c0 + blo);
        g_ph[(size_t)(rowg + 8) * 32 + n * 4 + (lane & 3)] =
            cvt_h2(c3 + bhi, c2 + blo);
    }
}

// ---------------------------------------------------------------------------
// Kernel 2: fused additive attention (tightened inner loop).
// ---------------------------------------------------------------------------
// smem layout (u32 word indices)
#define SM_KV    0        // 9216
#define SM_W2H   9216     // 32
#define SM_S     9248     // 4352 f32 scores pitch 17; later p_h f16 pitch 264
#define SM_PMAX  13600    // 16 x 17
#define SM_PSUM  13872    // 16 x 17
#define SM_M     14144    // 16
#define SM_R     14160    // 16
#define SM_WORDS 14176    // 56704 bytes

#define P_PITCH_W 132     // p_h pitch in u32 words (264 f16, 528B)
#define V_PITCH_W 36      // v_h pitch in u32 words (72 f16, 144B)

__global__ __launch_bounds__(256, 4) void attn_kernel(
    const float* __restrict__ v,
    const float* __restrict__ vs_w,
    float* __restrict__ out,        // [BH,256,64]
    float* __restrict__ attn_out)   // [BH,256,256]
{
    extern __shared__ float sm[];
    uint32_t* kv_u  = (uint32_t*)sm + SM_KV;
    uint32_t* w2h_s = (uint32_t*)sm + SM_W2H;
    float*    s_s   = sm + SM_S;
    uint32_t* ph_u  = (uint32_t*)sm + SM_S;   // overlays s_s after scores die
    float* pmax = sm + SM_PMAX;
    float* psum = sm + SM_PSUM;
    float* m_s  = sm + SM_M;
    float* r_s  = sm + SM_R;

    const int tid  = threadIdx.x;
    const int wid  = tid >> 5;
    const int lane = tid & 31;
    const int bh   = blockIdx.x >> 4;
    const int qt   = blockIdx.x & 15;

    // ---- phase 0: stage kp (f16x2, pitch 32 words) + w --------------------
    {
        const uint4* src = (const uint4*)(g_ph + (size_t)(NQROWS + bh * LK_) * 32);
        uint4* dst = (uint4*)kv_u;
#pragma unroll
        for (int i = 0; i < 8; i++) dst[tid + 256 * i] = src[tid + 256 * i];
    }
    if (tid < 32) w2h_s[tid] = cvt_h2(vs_w[2 * tid + 1], vs_w[2 * tid]);
    __syncthreads();

    // ---- phase 1: scores ---------------------------------------------------
    const int q    = lane & 15;
    const int kh   = lane >> 4;
    const int kbase = wid * 32 + kh * 16;
    const int qrow = bh * LQ_ + qt * 16 + q;
    float cm = -1e30f;

#pragma unroll 1
    for (int h = 0; h < 2; h++) {
        uint32_t qph[16], wh[16];
        {
            const uint4* qs = (const uint4*)(g_ph + (size_t)qrow * 32 + h * 16);
#pragma unroll
            for (int j = 0; j < 4; j++) {
                uint4 t = qs[j];
                qph[4*j] = t.x; qph[4*j+1] = t.y; qph[4*j+2] = t.z; qph[4*j+3] = t.w;
            }
        }
#pragma unroll
        for (int j = 0; j < 16; j++) wh[j] = w2h_s[h * 16 + j];

        const uint4* kr = (const uint4*)(kv_u + kbase * 32 + h * 16);
        float* srow = s_s + kbase * 17 + q;
#pragma unroll 2
        for (int kk = 0; kk < 16; kk++, kr += 8, srow += 17) {
            const uint4 c0 = kr[0], c1 = kr[1], c2 = kr[2], c3 = kr[3];
            uint32_t h0 = 0, h1 = 0, g0 = 0, g1 = 0;
            h0 = hfma2(tanh2(hadd2(qph[0],  c0.x)), wh[0],  h0);
            h1 = hfma2(tanh2(hadd2(qph[1],  c0.y)), wh[1],  h1);
            h0 = hfma2(tanh2(hadd2(qph[2],  c0.z)), wh[2],  h0);
            h1 = hfma2(tanh2(hadd2(qph[3],  c0.w)), wh[3],  h1);
            h0 = hfma2(tanh2(hadd2(qph[4],  c1.x)), wh[4],  h0);
            h1 = hfma2(tanh2(hadd2(qph[5],  c1.y)), wh[5],  h1);
            h0 = hfma2(tanh2(hadd2(qph[6],  c1.z)), wh[6],  h0);
            h1 = hfma2(tanh2(hadd2(qph[7],  c1.w)), wh[7],  h1);
            g0 = hfma2(tanh2(hadd2(qph[8],  c2.x)), wh[8],  g0);
            g1 = hfma2(tanh2(hadd2(qph[9],  c2.y)), wh[9],  g1);
            g0 = hfma2(tanh2(hadd2(qph[10], c2.z)), wh[10], g0);
            g1 = hfma2(tanh2(hadd2(qph[11], c2.w)), wh[11], g1);
            g0 = hfma2(tanh2(hadd2(qph[12], c3.x)), wh[12], g0);
            g1 = hfma2(tanh2(hadd2(qph[13], c3.y)), wh[13], g1);
            g0 = hfma2(tanh2(hadd2(qph[14], c3.z)), wh[14], g0);
            g1 = hfma2(tanh2(hadd2(qph[15], c3.w)), wh[15], g1);
            const uint32_t hs = hadd2(h0, h1);
            const uint32_t gs = hadd2(g0, g1);
            float f0, f1, f2, f3;
            h2tof(hs, f0, f1); h2tof(gs, f2, f3);
            const float part = (f0 + f1) + (f2 + f3);

            if (h == 0) {
                *srow = part;
            } else {
                const float sc = *srow + part;
                *srow = sc;
                cm = fmaxf(cm, sc);
            }
        }
    }
    pmax[q * 17 + wid * 2 + kh] = cm;
    __syncthreads();

    // ---- phase 2: row max + stage v as f16 (pitch 72 f16, overwrites kp) --
    if (tid < 16) {
        float m = pmax[tid * 17];
#pragma unroll
        for (int i = 1; i < 16; i++) m = fmaxf(m, pmax[tid * 17 + i]);
        m_s[tid] = m;
    }
    {
        const float4* vsrc = (const float4*)(v + (size_t)bh * (LK_ * DK_));
#pragma unroll
        for (int i = 0; i < 16; i++) {
            const int idx = tid + 256 * i;           // 0..4095; k=idx>>4, c=idx&15
            float4 t = vsrc[idx];
            const int kk2 = idx >> 4, c = idx & 15;
            uint32_t w0 = cvt_h2(t.y, t.x);
            uint32_t w1 = cvt_h2(t.w, t.z);
            *(uint2*)(kv_u + kk2 * V_PITCH_W + 2 * c) = make_uint2(w0, w1);
        }
    }
    __syncthreads();

    // ---- phase 3: exp into registers, partial sums -------------------------
    const int qe = tid & 15;
    const int ks = tid >> 4;
    float e[16];
    {
        const float m = m_s[qe];
        float s = 0.f;
#pragma unroll
        for (int kk = 0; kk < 16; kk++) {
            const int k = ks * 16 + kk;
            const float ev = ex2_fast((s_s[k * 17 + qe] - m) * LOG2E);
            e[kk] = ev;
            s += ev;
        }
        psum[qe * 17 + ks] = s;
    }
    __syncthreads();
    if (tid < 16) {
        float l = psum[tid * 17];
#pragma unroll
        for (int i = 1; i < 16; i++) l += psum[tid * 17 + i];
        r_s[tid] = 1.0f / l;
    }
    __syncthreads();

    // ---- phase 4: write attn (from regs) + p_h f16 (overlays s_s) ---------
    {
        const float r = r_s[qe];
        float4* ab = (float4*)(attn_out + (size_t)(bh * LQ_ + qt * 16 + qe) * LK_
                               + ks * 16);
#pragma unroll
        for (int j = 0; j < 4; j++)
            ab[j] = make_float4(e[4*j] * r, e[4*j+1] * r, e[4*j+2] * r, e[4*j+3] * r);
#pragma unroll
        for (int j = 0; j < 8; j++)
            ph_u[qe * P_PITCH_W + ks * 8 + j] = cvt_h2(e[2*j+1] * r, e[2*j] * r);
    }
    __syncthreads();

    // ---- phase 5: epilogue GEMM out[16q x 64d] = p[16x256] @ v[256x64] ----
    {
        const int d0 = wid * 8;
        float c0 = 0.f, c1 = 0.f, c2 = 0.f, c3 = 0.f;
        const uint32_t pa_base = smem_u32(ph_u) + ((lane & 15) * P_PITCH_W) * 4;
        const uint32_t vb_base = smem_u32(kv_u) + ((lane & 15) * V_PITCH_W + (d0 >> 1)) * 4;
#pragma unroll
        for (int kb = 0; kb < 16; kb++) {
            uint32_t a0, a1, a2, a3, b0, b1;
            const uint32_t pa = pa_base + (kb * 8 + (lane >> 4) * 4) * 4;
            asm volatile("ldmatrix.sync.aligned.m8n8.x4.shared.b16 {%0,%1,%2,%3}, [%4];"
                         : "=r"(a0), "=r"(a1), "=r"(a2), "=r"(a3) : "r"(pa));
            const uint32_t vb = vb_base + (kb * 16 * V_PITCH_W) * 4;
            asm volatile("ldmatrix.sync.aligned.m8n8.x2.trans.shared.b16 {%0,%1}, [%2];"
                         : "=r"(b0), "=r"(b1) : "r"(vb));
            asm volatile("mma.sync.aligned.m16n8k16.row.col.f32.f16.f16.f32 "
                         "{%0,%1,%2,%3},{%4,%5,%6,%7},{%8,%9},{%0,%1,%2,%3};"
                         : "+f"(c0), "+f"(c1), "+f"(c2), "+f"(c3)
                         : "r"(a0), "r"(a1), "r"(a2), "r"(a3), "r"(b0), "r"(b1));
        }
        const int qr = lane >> 2;
        const int dc = d0 + 2 * (lane & 3);
        float* ob = out + (size_t)(bh * LQ_ + qt * 16) * DK_;
        *(float2*)(ob + qr * DK_ + dc)       = make_float2(c0, c1);
        *(float2*)(ob + (qr + 8) * DK_ + dc) = make_float2(c2, c3);
    }
}

// ---------------------------------------------------------------------------
extern "C" void kernel_launch(void* const* d_in, const int* in_sizes, int n_in,
                              void* d_out, int out_size)
{
    const float* q    = (const float*)d_in[0];
    const float* k    = (const float*)d_in[1];
    const float* v    = (const float*)d_in[2];
    const float* Wq_w = (const float*)d_in[3];
    const float* Wq_b = (const float*)d_in[4];
    const float* Wk_w = (const float*)d_in[5];
    const float* Wk_b = (const float*)d_in[6];
    const float* vs_w = (const float*)d_in[7];
    // vs_b (d_in[8]) is softmax-invariant: unused.

    float* out  = (float*)d_out;                            // [B,H,LQ,DK]
    float* attn = (float*)d_out + (size_t)BH_ * LQ_ * DK_;  // [B,H,LQ,LK]

    const int smem_bytes = SM_WORDS * 4;
    cudaFuncSetAttribute(attn_kernel, cudaFuncAttributeMaxDynamicSharedMemorySize,
                         smem_bytes);

    proj_kernel<<<256, 128>>>(q, k, Wq_w, Wq_b, Wk_w, Wk_b);
    attn_kernel<<<512, 256, smem_bytes>>>(v, vs_w, out, attn);
}